// round 5
// baseline (speedup 1.0000x reference)
#include <cuda_runtime.h>
#include <cuda_bf16.h>
#include <math.h>

// Problem constants
#define B_      2
#define CIN     48
#define HH      512
#define WW      512
#define HW      (512*512)
#define CQ      144      // 3*DIM
#define HEADS   8
#define CSUB    6        // DIM/HEADS
#define NB      4
#define H1      128
#define NTOK    16384    // H1*W1
#define CB      96       // CSUB*NB*NB
#define NCHUNK  16       // split-K chunks for gram
#define BHTOT   16       // B*HEADS

typedef unsigned long long u64;

// packed fp32x2 FMA: d = a*b + d. Bitwise == 2x fmaf.
__device__ __forceinline__ void ffma2(u64& d, u64 a, u64 b) {
    asm("fma.rn.f32x2 %0, %1, %2, %0;" : "+l"(d) : "l"(a), "l"(b));
}
__device__ __forceinline__ u64 pack2(float lo, float hi) {
    u64 r; asm("mov.b64 %0, {%1, %2};" : "=l"(r) : "f"(lo), "f"(hi)); return r;
}
__device__ __forceinline__ float2 unpack2(u64 v) {
    float2 r; asm("mov.b64 {%0, %1}, %2;" : "=f"(r.x), "=f"(r.y) : "l"(v)); return r;
}
__device__ __forceinline__ void cp16(void* smem_ptr, const void* gptr) {
    unsigned s = (unsigned)__cvta_generic_to_shared(smem_ptr);
    asm volatile("cp.async.cg.shared.global [%0], [%1], 16;" :: "r"(s), "l"(gptr));
}
__device__ __forceinline__ void cp_wait_all() {
    asm volatile("cp.async.commit_group;\n\tcp.async.wait_group 0;" ::: "memory");
}

// ---------------- scratch (device globals; no allocations allowed) ----------------
__device__ float g_qkv[(size_t)B_*CQ*HW];              // after 1x1 conv
__device__ float g_q [(size_t)BHTOT*CB*NTOK];          // after dw, block layout
__device__ float g_k [(size_t)BHTOT*CB*NTOK];
__device__ float g_v [(size_t)BHTOT*CB*NTOK];
__device__ float g_Spart[(size_t)BHTOT*NCHUNK*CB*CB];  // split-K gram partials
__device__ float g_ssqpart[2*BHTOT*NCHUNK*CB];         // row sum-sq partials (q then k)
__device__ float g_attn[(size_t)BHTOT*CB*CB];          // softmaxed attention
__device__ float g_out1[(size_t)B_*CIN*HW];            // attn output, NCHW

// ---------------- K1: 1x1 conv qkv  (GEMM [144x48] @ [48 x HW]), f32x2 ----------------
// grid (3, HW/256, B): oc-third on x so sibling blocks (same px) are adjacent -> share x via L2.
// Whole 48-ic X tile preloaded via cp.async (one long-MLP phase), then pure compute.
__global__ void __launch_bounds__(256, 3) k_qkv(const float* __restrict__ x, const float* __restrict__ wq) {
    __shared__ __align__(16) float Xs[48][256];   // 48 KB
    __shared__ __align__(16) u64   W2[48][48];    // 18.4 KB, weights duplicated (w,w)
    const int b   = blockIdx.z;
    const int oc0 = blockIdx.x * 48;
    const int px0 = blockIdx.y * 256;
    const int tid = threadIdx.x;
    const int lane = tid & 31;
    const int wgrp = tid >> 5;        // 0..7 -> oc group of 6

    const float* xb = x + (size_t)b*CIN*HW + px0;
    for (int i = tid; i < 48*64; i += 256) {
        int row = i >> 6, c4 = (i & 63) * 4;
        cp16(&Xs[row][c4], xb + (size_t)row*HW + c4);
    }
    for (int i = tid; i < 48*48; i += 256) {
        int oc = i / 48, ic = i % 48;
        float w = wq[(oc0 + oc)*48 + ic];
        W2[oc][ic] = pack2(w, w);
    }
    cp_wait_all();
    __syncthreads();

    u64 acc[6][4];
#pragma unroll
    for (int i = 0; i < 6; ++i)
#pragma unroll
        for (int j = 0; j < 4; ++j) acc[i][j] = 0ull;

#pragma unroll 4
    for (int k2 = 0; k2 < 24; ++k2) {
        const int k = 2*k2;
        u64 bv0[4], bv1[4];
#pragma unroll
        for (int j = 0; j < 4; ++j) {
            bv0[j] = *(const u64*)&Xs[k  ][2*lane + 64*j];
            bv1[j] = *(const u64*)&Xs[k+1][2*lane + 64*j];
        }
#pragma unroll
        for (int i = 0; i < 6; ++i) {
            const u64* wp2 = (const u64*)&W2[wgrp*6 + i][k];  // LDS.128 pair, broadcast
            u64 a0 = wp2[0], a1 = wp2[1];
#pragma unroll
            for (int j = 0; j < 4; ++j) { ffma2(acc[i][j], a0, bv0[j]); ffma2(acc[i][j], a1, bv1[j]); }
        }
    }
    float* outb = g_qkv + (size_t)b*CQ*HW;
#pragma unroll
    for (int i = 0; i < 6; ++i) {
        int oc = oc0 + wgrp*6 + i;
#pragma unroll
        for (int j = 0; j < 4; ++j)
            *(float2*)&outb[(size_t)oc*HW + px0 + 2*lane + 64*j] = unpack2(acc[i][j]);
    }
}

// ---------------- K2: 3x3 depthwise (zero pad) + scatter into block layout ----------------
// grid (8,16,B*CQ), block 256; 64x32 tile (halo 66x34)
__global__ void k_dw(const float* __restrict__ dw) {
    __shared__ float tile[34][66];
    const int ch = blockIdx.z % CQ;
    const int b  = blockIdx.z / CQ;
    const int y0 = blockIdx.y * 32;
    const int x0 = blockIdx.x * 64;
    const int tid = threadIdx.x;

    const float* src = g_qkv + ((size_t)b*CQ + ch)*HW;
    for (int i = tid; i < 34*66; i += 256) {
        int yy = i / 66 - 1 + y0;
        int xx = i % 66 - 1 + x0;
        float v = 0.f;
        if (yy >= 0 && yy < HH && xx >= 0 && xx < WW) v = src[yy*WW + xx];
        tile[i/66][i%66] = v;
    }
    float w[9];
#pragma unroll
    for (int t = 0; t < 9; ++t) w[t] = dw[ch*9 + t];
    __syncthreads();

    const int part = ch / 48;            // 0=q 1=k 2=v
    const int chh  = ch % 48;
    const int head = chh / CSUB;
    const int ci   = chh % CSUB;
    float* base = (part == 0) ? g_q : (part == 1) ? g_k : g_v;
    float* dst = base + (size_t)(b*HEADS + head)*CB*NTOK;

    for (int p = tid; p < 64*32; p += 256) {
        int ly = p >> 6, lx = p & 63;
        float s = 0.f;
#pragma unroll
        for (int dy = 0; dy < 3; ++dy)
#pragma unroll
            for (int dx = 0; dx < 3; ++dx)
                s = fmaf(w[dy*3 + dx], tile[ly + dy][lx + dx], s);
        int y = y0 + ly, xg = x0 + lx;
        int row = ci*16 + (y & 3)*4 + (xg & 3);
        int n   = (y >> 2)*H1 + (xg >> 2);
        dst[(size_t)row*NTOK + n] = s;
    }
}

// ---------------- K3: split-K gram, f32x2, register-staged pipeline ----------------
// grid (NCHUNK, BHTOT), block 256. Thread computes 6 rows x 3 col-pairs of 96x96 tile.
__global__ void __launch_bounds__(256, 2) k_gram() {
    __shared__ __align__(16) u64   Qd[32][97];   // q duplicated (v,v)
    __shared__ float Ks[32][98];
    const int chunk = blockIdx.x;
    const int bh    = blockIdx.y;
    const int tid = threadIdx.x;
    const int lane = tid & 31;
    const int w    = tid >> 5;
    const int rowg = tid >> 4;   // 0..15
    const int colg = tid & 15;   // 0..15
    const int n0 = chunk * (NTOK / NCHUNK);

    const float* Q  = g_q + (size_t)bh*CB*NTOK;
    const float* Kp = g_k + (size_t)bh*CB*NTOK;

    u64 acc[6][3];
#pragma unroll
    for (int i = 0; i < 6; ++i)
#pragma unroll
        for (int j = 0; j < 3; ++j) acc[i][j] = 0ull;
    float sq[12], sk[12];
#pragma unroll
    for (int t = 0; t < 12; ++t) { sq[t] = 0.f; sk[t] = 0.f; }

    float qr[12], kr[12];
#pragma unroll
    for (int t = 0; t < 12; ++t) {          // preload iter 0
        int r = w + 8*t;
        qr[t] = Q [(size_t)r*NTOK + n0 + lane];
        kr[t] = Kp[(size_t)r*NTOK + n0 + lane];
    }

    const int NIT = (NTOK / NCHUNK) / 32;   // 32
    for (int kt = 0; kt < NIT; ++kt) {
        __syncthreads();                    // prev compute done reading smem
#pragma unroll
        for (int t = 0; t < 12; ++t) {
            int r = w + 8*t;
            Qd[lane][r] = pack2(qr[t], qr[t]);
            Ks[lane][r] = kr[t];
            sq[t] = fmaf(qr[t], qr[t], sq[t]);
            sk[t] = fmaf(kr[t], kr[t], sk[t]);
        }
        __syncthreads();
        if (kt + 1 < NIT) {                 // loads in flight during compute below
            int base = n0 + (kt + 1)*32 + lane;
#pragma unroll
            for (int t = 0; t < 12; ++t) {
                int r = w + 8*t;
                qr[t] = Q [(size_t)r*NTOK + base];
                kr[t] = Kp[(size_t)r*NTOK + base];
            }
        }
#pragma unroll
        for (int k = 0; k < 32; ++k) {
            u64 bv[3];
#pragma unroll
            for (int j = 0; j < 3; ++j) bv[j] = *(const u64*)&Ks[k][colg*6 + 2*j];
#pragma unroll
            for (int i = 0; i < 6; ++i) {
                u64 a2 = Qd[k][rowg*6 + i];
#pragma unroll
                for (int j = 0; j < 3; ++j) ffma2(acc[i][j], a2, bv[j]);
            }
        }
    }
    float* Sp = g_Spart + ((size_t)bh*NCHUNK + chunk)*CB*CB;
#pragma unroll
    for (int i = 0; i < 6; ++i)
#pragma unroll
        for (int j = 0; j < 3; ++j)
            *(float2*)&Sp[(rowg*6 + i)*CB + colg*6 + 2*j] = unpack2(acc[i][j]);

#pragma unroll
    for (int t = 0; t < 12; ++t) {
        float s1 = sq[t], s2 = sk[t];
#pragma unroll
        for (int off = 16; off > 0; off >>= 1) {
            s1 += __shfl_xor_sync(0xffffffffu, s1, off);
            s2 += __shfl_xor_sync(0xffffffffu, s2, off);
        }
        if (lane == 0) {
            int r = w + 8*t;
            g_ssqpart[((0*BHTOT + bh)*NCHUNK + chunk)*CB + r] = s1;
            g_ssqpart[((1*BHTOT + bh)*NCHUNK + chunk)*CB + r] = s2;
        }
    }
}

// ---------------- K4: reduce partials, scale by 1/(|q||k|)*temp, softmax ----------------
__global__ void k_soft(const float* __restrict__ temperature) {
    __shared__ float invk[96];
    __shared__ float invq[8];
    const int bh = blockIdx.y;
    const int rb = blockIdx.x * 8;
    const int head = bh & 7;
    const int tid = threadIdx.x;
    const int lane = tid & 31;
    const int w = tid >> 5;

    if (tid < 96) {
        float sumk = 0.f;
        for (int c = 0; c < NCHUNK; ++c)
            sumk += g_ssqpart[((1*BHTOT + bh)*NCHUNK + c)*CB + tid];
        invk[tid] = 1.f / fmaxf(sqrtf(sumk), 1e-12f);
    } else if (tid >= 128 && tid < 136) {
        int r = rb + tid - 128;
        float sumq = 0.f;
        for (int c = 0; c < NCHUNK; ++c)
            sumq += g_ssqpart[((0*BHTOT + bh)*NCHUNK + c)*CB + r];
        invq[tid - 128] = 1.f / fmaxf(sqrtf(sumq), 1e-12f);
    }
    __syncthreads();
    const float temp = temperature[head];
    const float* Sp = g_Spart + (size_t)bh*NCHUNK*CB*CB;
    float* Ao = g_attn + (size_t)bh*CB*CB;

    const int row = rb + w;
    float v[3];
#pragma unroll
    for (int j = 0; j < 3; ++j) {
        int col = lane + 32*j;
        float s = 0.f;
        for (int c = 0; c < NCHUNK; ++c) s += Sp[c*CB*CB + row*CB + col];
        v[j] = s * temp * invq[w] * invk[col];
    }
    float m = fmaxf(v[0], fmaxf(v[1], v[2]));
#pragma unroll
    for (int off = 16; off > 0; off >>= 1) m = fmaxf(m, __shfl_xor_sync(0xffffffffu, m, off));
    float e[3], sum = 0.f;
#pragma unroll
    for (int j = 0; j < 3; ++j) { e[j] = __expf(v[j] - m); sum += e[j]; }
#pragma unroll
    for (int off = 16; off > 0; off >>= 1) sum += __shfl_xor_sync(0xffffffffu, sum, off);
    float inv = 1.f / sum;
#pragma unroll
    for (int j = 0; j < 3; ++j) Ao[row*CB + lane + 32*j] = e[j] * inv;
}

// ---------------- K5: out = attn @ v, fused scatter, f32x2, pipelined ----------------
// grid (128, BHTOT), block 384. 8 iters of 12 k-rows; V staged through regs (1 float4/thread).
__global__ void __launch_bounds__(384, 2) k_av() {
    __shared__ __align__(16) u64   As2[CB*CB];     // attn duplicated: 73.7 KB
    __shared__ __align__(16) float Vs[12][128];    //  6 KB
    const int nt = blockIdx.x;       // 0..127  (== h1)
    const int bh = blockIdx.y;
    const int b = bh >> 3, head = bh & 7;
    const int tid = threadIdx.x;
    const int rg = tid >> 5;         // 0..11 : rows rg*8..rg*8+7
    const int tg = tid & 31;         // token-pair lane
    const int vrow = tid >> 5;       // 0..11
    const int vc4  = (tid & 31) * 4;

    const float* A = g_attn + (size_t)bh*CB*CB;
    for (int i = tid; i < CB*CB; i += 384) {
        float a = A[i];
        As2[i] = pack2(a, a);
    }

    const float* V = g_v + (size_t)bh*CB*NTOK + nt*128;
    u64 acc[8][2];
#pragma unroll
    for (int i = 0; i < 8; ++i) { acc[i][0] = 0ull; acc[i][1] = 0ull; }

    float4 stage = *(const float4*)&V[(size_t)vrow*NTOK + vc4];   // iter 0

    for (int kc = 0; kc < 8; ++kc) {
        __syncthreads();
        *(float4*)&Vs[vrow][vc4] = stage;
        __syncthreads();
        if (kc + 1 < 8)
            stage = *(const float4*)&V[(size_t)((kc+1)*12 + vrow)*NTOK + vc4];
#pragma unroll
        for (int k = 0; k < 12; ++k) {
            u64 bv0 = *(const u64*)&Vs[k][2*tg];
            u64 bv1 = *(const u64*)&Vs[k][2*tg + 64];
#pragma unroll
            for (int i = 0; i < 8; ++i) {
                u64 a2 = As2[(rg*8 + i)*CB + kc*12 + k];
                ffma2(acc[i][0], a2, bv0);
                ffma2(acc[i][1], a2, bv1);
            }
        }
    }
    float* outb = g_out1 + (size_t)b*CIN*HW;
#pragma unroll
    for (int g = 0; g < 2; ++g) {
        int group = rg*2 + g;
        int ci = group >> 2, Nh = group & 3;
        int ch = head*CSUB + ci;
        int y  = nt*4 + Nh;
#pragma unroll
        for (int jp = 0; jp < 2; ++jp) {
            float2 p0 = unpack2(acc[g*4+0][jp]);
            float2 p1 = unpack2(acc[g*4+1][jp]);
            float2 p2 = unpack2(acc[g*4+2][jp]);
            float2 p3 = unpack2(acc[g*4+3][jp]);
            size_t base = ((size_t)ch*HH + y)*WW + (size_t)(2*tg + 64*jp)*4;
            *(float4*)&outb[base]     = make_float4(p0.x, p1.x, p2.x, p3.x);
            *(float4*)&outb[base + 4] = make_float4(p0.y, p1.y, p2.y, p3.y);
        }
    }
}

// ---------------- K6: 1x1 proj conv  (GEMM [48x48] @ [48 x HW]), f32x2, preload-all ----------------
__global__ void __launch_bounds__(256, 3) k_proj(const float* __restrict__ wp, float* __restrict__ out) {
    __shared__ __align__(16) float Xs[48][256];   // 48 KB
    __shared__ __align__(16) u64   W2[48][48];    // 18.4 KB
    const int b   = blockIdx.z;
    const int px0 = blockIdx.x * 256;
    const int tid = threadIdx.x;
    const int lane = tid & 31;
    const int wgrp = tid >> 5;

    const float* xb = g_out1 + (size_t)b*CIN*HW + px0;
    for (int i = tid; i < 48*64; i += 256) {
        int row = i >> 6, c4 = (i & 63) * 4;
        cp16(&Xs[row][c4], xb + (size_t)row*HW + c4);
    }
    for (int i = tid; i < 48*48; i += 256) {
        int oc = i / 48, ic = i % 48;
        float w = wp[oc*48 + ic];
        W2[oc][ic] = pack2(w, w);
    }
    cp_wait_all();
    __syncthreads();

    u64 acc[6][4];
#pragma unroll
    for (int i = 0; i < 6; ++i)
#pragma unroll
        for (int j = 0; j < 4; ++j) acc[i][j] = 0ull;

#pragma unroll 4
    for (int k2 = 0; k2 < 24; ++k2) {
        const int k = 2*k2;
        u64 bv0[4], bv1[4];
#pragma unroll
        for (int j = 0; j < 4; ++j) {
            bv0[j] = *(const u64*)&Xs[k  ][2*lane + 64*j];
            bv1[j] = *(const u64*)&Xs[k+1][2*lane + 64*j];
        }
#pragma unroll
        for (int i = 0; i < 6; ++i) {
            const u64* wp2 = (const u64*)&W2[wgrp*6 + i][k];
            u64 a0 = wp2[0], a1 = wp2[1];
#pragma unroll
            for (int j = 0; j < 4; ++j) { ffma2(acc[i][j], a0, bv0[j]); ffma2(acc[i][j], a1, bv1[j]); }
        }
    }
    float* ob = out + (size_t)b*CIN*HW;
#pragma unroll
    for (int i = 0; i < 6; ++i) {
        int oc = wgrp*6 + i;
#pragma unroll
        for (int j = 0; j < 4; ++j)
            *(float2*)&ob[(size_t)oc*HW + px0 + 2*lane + 64*j] = unpack2(acc[i][j]);
    }
}

// ---------------- launch ----------------
extern "C" void kernel_launch(void* const* d_in, const int* in_sizes, int n_in,
                              void* d_out, int out_size) {
    (void)in_sizes; (void)n_in; (void)out_size;
    const float* x      = (const float*)d_in[0];
    const float* qkv_w  = (const float*)d_in[1];
    const float* dw_w   = (const float*)d_in[2];
    const float* proj_w = (const float*)d_in[3];
    const float* temper = (const float*)d_in[4];
    float* out = (float*)d_out;

    k_qkv <<<dim3(3, HW/256, B_), 256>>>(x, qkv_w);
    k_dw  <<<dim3(8, 16, B_*CQ), 256>>>(dw_w);
    k_gram<<<dim3(NCHUNK, BHTOT), 256>>>();
    k_soft<<<dim3(12, BHTOT), 256>>>(temper);
    k_av  <<<dim3(NTOK/128, BHTOT), 384>>>();
    k_proj<<<dim3(HW/256, 1, B_), 256>>>(proj_w, out);
}

// round 6
// speedup vs baseline: 1.1403x; 1.1403x over previous
#include <cuda_runtime.h>
#include <cuda_bf16.h>
#include <math.h>
#include <stdint.h>

#define B_      2
#define CIN     48
#define HH      512
#define WW      512
#define HW      (512*512)
#define CQ      144
#define HEADS   8
#define CSUB    6
#define NB      4
#define H1      128
#define NTOK    16384
#define CB      96
#define NCHUNK  16
#define BHTOT   16

typedef unsigned long long u64;

__device__ __forceinline__ void ffma2(u64& d, u64 a, u64 b) {
    asm("fma.rn.f32x2 %0, %1, %2, %0;" : "+l"(d) : "l"(a), "l"(b));
}
__device__ __forceinline__ u64 pack2(float lo, float hi) {
    u64 r; asm("mov.b64 %0, {%1, %2};" : "=l"(r) : "f"(lo), "f"(hi)); return r;
}
__device__ __forceinline__ float2 unpack2(u64 v) {
    float2 r; asm("mov.b64 {%0, %1}, %2;" : "=f"(r.x), "=f"(r.y) : "l"(v)); return r;
}
__device__ __forceinline__ void cp16(void* smem_ptr, const void* gptr) {
    unsigned s = (unsigned)__cvta_generic_to_shared(smem_ptr);
    asm volatile("cp.async.cg.shared.global [%0], [%1], 16;" :: "r"(s), "l"(gptr));
}
__device__ __forceinline__ void cp_wait_all() {
    asm volatile("cp.async.commit_group;\n\tcp.async.wait_group 0;" ::: "memory");
}
// ---- warp mma helpers (bf16, TN) ----
__device__ __forceinline__ void ldsm_x4(uint32_t* r, uint32_t a) {
    asm volatile("ldmatrix.sync.aligned.m8n8.x4.shared.b16 {%0,%1,%2,%3}, [%4];"
        : "=r"(r[0]), "=r"(r[1]), "=r"(r[2]), "=r"(r[3]) : "r"(a));
}
__device__ __forceinline__ void ldsm_x2(uint32_t* r, uint32_t a) {
    asm volatile("ldmatrix.sync.aligned.m8n8.x2.shared.b16 {%0,%1}, [%2];"
        : "=r"(r[0]), "=r"(r[1]) : "r"(a));
}
__device__ __forceinline__ void mma_bf16(float* c, const uint32_t* a, const uint32_t* b) {
    asm volatile("mma.sync.aligned.m16n8k16.row.col.f32.bf16.bf16.f32 "
        "{%0,%1,%2,%3}, {%4,%5,%6,%7}, {%8,%9}, {%0,%1,%2,%3};"
        : "+f"(c[0]), "+f"(c[1]), "+f"(c[2]), "+f"(c[3])
        : "r"(a[0]), "r"(a[1]), "r"(a[2]), "r"(a[3]), "r"(b[0]), "r"(b[1]));
}

// ---------------- scratch ----------------
__device__ float g_qkv[(size_t)B_*CQ*HW];
__device__ float g_q [(size_t)BHTOT*CB*NTOK];
__device__ float g_k [(size_t)BHTOT*CB*NTOK];
__device__ float g_v [(size_t)BHTOT*CB*NTOK];
__device__ float g_Spart[(size_t)BHTOT*NCHUNK*CB*CB];
__device__ float g_ssqpart[2*BHTOT*NCHUNK*CB];
__device__ float g_attn[(size_t)BHTOT*CB*CB];
__device__ float g_out1[(size_t)B_*CIN*HW];

// ---------------- K1: 1x1 conv qkv ----------------
__global__ void __launch_bounds__(256, 3) k_qkv(const float* __restrict__ x, const float* __restrict__ wq) {
    __shared__ __align__(16) float Xs[48][256];
    __shared__ __align__(16) u64   W2[48][48];
    const int b   = blockIdx.z;
    const int oc0 = blockIdx.x * 48;
    const int px0 = blockIdx.y * 256;
    const int tid = threadIdx.x;
    const int lane = tid & 31;
    const int wgrp = tid >> 5;

    const float* xb = x + (size_t)b*CIN*HW + px0;
    for (int i = tid; i < 48*64; i += 256) {
        int row = i >> 6, c4 = (i & 63) * 4;
        cp16(&Xs[row][c4], xb + (size_t)row*HW + c4);
    }
    for (int i = tid; i < 48*48; i += 256) {
        int oc = i / 48, ic = i % 48;
        float w = wq[(oc0 + oc)*48 + ic];
        W2[oc][ic] = pack2(w, w);
    }
    cp_wait_all();
    __syncthreads();

    u64 acc[6][4];
#pragma unroll
    for (int i = 0; i < 6; ++i)
#pragma unroll
        for (int j = 0; j < 4; ++j) acc[i][j] = 0ull;

#pragma unroll 4
    for (int k2 = 0; k2 < 24; ++k2) {
        const int k = 2*k2;
        u64 bv0[4], bv1[4];
#pragma unroll
        for (int j = 0; j < 4; ++j) {
            bv0[j] = *(const u64*)&Xs[k  ][2*lane + 64*j];
            bv1[j] = *(const u64*)&Xs[k+1][2*lane + 64*j];
        }
#pragma unroll
        for (int i = 0; i < 6; ++i) {
            const u64* wp2 = (const u64*)&W2[wgrp*6 + i][k];
            u64 a0 = wp2[0], a1 = wp2[1];
#pragma unroll
            for (int j = 0; j < 4; ++j) { ffma2(acc[i][j], a0, bv0[j]); ffma2(acc[i][j], a1, bv1[j]); }
        }
    }
    float* outb = g_qkv + (size_t)b*CQ*HW;
#pragma unroll
    for (int i = 0; i < 6; ++i) {
        int oc = oc0 + wgrp*6 + i;
#pragma unroll
        for (int j = 0; j < 4; ++j)
            *(float2*)&outb[(size_t)oc*HW + px0 + 2*lane + 64*j] = unpack2(acc[i][j]);
    }
}

// ---------------- K2: 3x3 depthwise + block scatter ----------------
__global__ void k_dw(const float* __restrict__ dw) {
    __shared__ float tile[34][66];
    const int ch = blockIdx.z % CQ;
    const int b  = blockIdx.z / CQ;
    const int y0 = blockIdx.y * 32;
    const int x0 = blockIdx.x * 64;
    const int tid = threadIdx.x;

    const float* src = g_qkv + ((size_t)b*CQ + ch)*HW;
    for (int i = tid; i < 34*66; i += 256) {
        int yy = i / 66 - 1 + y0;
        int xx = i % 66 - 1 + x0;
        float v = 0.f;
        if (yy >= 0 && yy < HH && xx >= 0 && xx < WW) v = src[yy*WW + xx];
        tile[i/66][i%66] = v;
    }
    float w[9];
#pragma unroll
    for (int t = 0; t < 9; ++t) w[t] = dw[ch*9 + t];
    __syncthreads();

    const int part = ch / 48;
    const int chh  = ch % 48;
    const int head = chh / CSUB;
    const int ci   = chh % CSUB;
    float* base = (part == 0) ? g_q : (part == 1) ? g_k : g_v;
    float* dst = base + (size_t)(b*HEADS + head)*CB*NTOK;

    for (int p = tid; p < 64*32; p += 256) {
        int ly = p >> 6, lx = p & 63;
        float s = 0.f;
#pragma unroll
        for (int dy = 0; dy < 3; ++dy)
#pragma unroll
            for (int dx = 0; dx < 3; ++dx)
                s = fmaf(w[dy*3 + dx], tile[ly + dy][lx + dx], s);
        int y = y0 + ly, xg = x0 + lx;
        int row = ci*16 + (y & 3)*4 + (xg & 3);
        int n   = (y >> 2)*H1 + (xg >> 2);
        dst[(size_t)row*NTOK + n] = s;
    }
}

// ---------------- K3: gram via mma.sync bf16 hi/lo split ----------------
// grid (NCHUNK, BHTOT), block 256 = 8 warps (2 M x 4 N). Warp tile 48x24 (3x3 frags).
// Tiles [96 rows][32 k] bf16 at pitch 40 halves (80B rows -> LDSM conflict-free).
#define GP 40
__global__ void __launch_bounds__(256, 2) k_gram() {
    __shared__ __nv_bfloat16 Qh[96*GP], Ql[96*GP], Kh[96*GP], Kl[96*GP];
    const int chunk = blockIdx.x, bh = blockIdx.y;
    const int tid = threadIdx.x, lane = tid & 31, w = tid >> 5;
    const int wm = w >> 2, wn = w & 3;            // warp tile origin (wm*48, wn*24)
    const int n0 = chunk * (NTOK / NCHUNK);

    const float* Q  = g_q + (size_t)bh*CB*NTOK;
    const float* Kp = g_k + (size_t)bh*CB*NTOK;

    float acc[9][4];
#pragma unroll
    for (int t = 0; t < 9; ++t) { acc[t][0]=0.f; acc[t][1]=0.f; acc[t][2]=0.f; acc[t][3]=0.f; }
    float sq[12], sk[12];
#pragma unroll
    for (int t = 0; t < 12; ++t) { sq[t] = 0.f; sk[t] = 0.f; }

    float qr[12], kr[12];
#pragma unroll
    for (int t = 0; t < 12; ++t) {
        int r = w + 8*t;
        qr[t] = Q [(size_t)r*NTOK + n0 + lane];
        kr[t] = Kp[(size_t)r*NTOK + n0 + lane];
    }

    const int NIT = (NTOK / NCHUNK) / 32;   // 32 iterations of 32 k-columns
    for (int kt = 0; kt < NIT; ++kt) {
        __syncthreads();
#pragma unroll
        for (int t = 0; t < 12; ++t) {
            int r = w + 8*t;
            float qv = qr[t], kv = kr[t];
            __nv_bfloat16 qh = __float2bfloat16(qv);
            __nv_bfloat16 kh = __float2bfloat16(kv);
            Qh[r*GP + lane] = qh;
            Ql[r*GP + lane] = __float2bfloat16(qv - __bfloat162float(qh));
            Kh[r*GP + lane] = kh;
            Kl[r*GP + lane] = __float2bfloat16(kv - __bfloat162float(kh));
            sq[t] = fmaf(qv, qv, sq[t]);
            sk[t] = fmaf(kv, kv, sk[t]);
        }
        __syncthreads();
        if (kt + 1 < NIT) {
            int base = n0 + (kt + 1)*32 + lane;
#pragma unroll
            for (int t = 0; t < 12; ++t) {
                int r = w + 8*t;
                qr[t] = Q [(size_t)r*NTOK + base];
                kr[t] = Kp[(size_t)r*NTOK + base];
            }
        }
#pragma unroll
        for (int ks = 0; ks < 2; ++ks) {
            const int k0 = ks*16;
            uint32_t ah[3][4], al[3][4], bhF[3][2], blF[3][2];
            const int arow = (lane & 15), acol = k0 + ((lane >> 4) << 3);
            const int brow = (lane & 7),  bcol = k0 + (((lane >> 3) & 1) << 3);
#pragma unroll
            for (int f = 0; f < 3; ++f) {
                int off = (wm*48 + f*16 + arow)*GP + acol;
                ldsm_x4(ah[f], (uint32_t)__cvta_generic_to_shared(&Qh[off]));
                ldsm_x4(al[f], (uint32_t)__cvta_generic_to_shared(&Ql[off]));
            }
#pragma unroll
            for (int g = 0; g < 3; ++g) {
                int off = (wn*24 + g*8 + brow)*GP + bcol;
                ldsm_x2(bhF[g], (uint32_t)__cvta_generic_to_shared(&Kh[off]));
                ldsm_x2(blF[g], (uint32_t)__cvta_generic_to_shared(&Kl[off]));
            }
#pragma unroll
            for (int f = 0; f < 3; ++f)
#pragma unroll
                for (int g = 0; g < 3; ++g) {
                    mma_bf16(acc[f*3+g], ah[f], bhF[g]);
                    mma_bf16(acc[f*3+g], ah[f], blF[g]);
                    mma_bf16(acc[f*3+g], al[f], bhF[g]);
                }
        }
    }
    float* Sp = g_Spart + ((size_t)bh*NCHUNK + chunk)*CB*CB;
#pragma unroll
    for (int f = 0; f < 3; ++f)
#pragma unroll
        for (int g = 0; g < 3; ++g) {
            int row = wm*48 + f*16 + (lane >> 2);
            int col = wn*24 + g*8 + (lane & 3)*2;
            float* c = acc[f*3+g];
            *(float2*)&Sp[row*CB + col]     = make_float2(c[0], c[1]);
            *(float2*)&Sp[(row+8)*CB + col] = make_float2(c[2], c[3]);
        }
#pragma unroll
    for (int t = 0; t < 12; ++t) {
        float s1 = sq[t], s2 = sk[t];
#pragma unroll
        for (int off = 16; off > 0; off >>= 1) {
            s1 += __shfl_xor_sync(0xffffffffu, s1, off);
            s2 += __shfl_xor_sync(0xffffffffu, s2, off);
        }
        if (lane == 0) {
            int r = w + 8*t;
            g_ssqpart[((0*BHTOT + bh)*NCHUNK + chunk)*CB + r] = s1;
            g_ssqpart[((1*BHTOT + bh)*NCHUNK + chunk)*CB + r] = s2;
        }
    }
}

// ---------------- K4: reduce + normalize + softmax ----------------
__global__ void k_soft(const float* __restrict__ temperature) {
    __shared__ float invk[96];
    __shared__ float invq[8];
    const int bh = blockIdx.y;
    const int rb = blockIdx.x * 8;
    const int head = bh & 7;
    const int tid = threadIdx.x;
    const int lane = tid & 31;
    const int w = tid >> 5;

    if (tid < 96) {
        float sumk = 0.f;
        for (int c = 0; c < NCHUNK; ++c)
            sumk += g_ssqpart[((1*BHTOT + bh)*NCHUNK + c)*CB + tid];
        invk[tid] = 1.f / fmaxf(sqrtf(sumk), 1e-12f);
    } else if (tid >= 128 && tid < 136) {
        int r = rb + tid - 128;
        float sumq = 0.f;
        for (int c = 0; c < NCHUNK; ++c)
            sumq += g_ssqpart[((0*BHTOT + bh)*NCHUNK + c)*CB + r];
        invq[tid - 128] = 1.f / fmaxf(sqrtf(sumq), 1e-12f);
    }
    __syncthreads();
    const float temp = temperature[head];
    const float* Sp = g_Spart + (size_t)bh*NCHUNK*CB*CB;
    float* Ao = g_attn + (size_t)bh*CB*CB;

    const int row = rb + w;
    float v[3];
#pragma unroll
    for (int j = 0; j < 3; ++j) {
        int col = lane + 32*j;
        float s = 0.f;
        for (int c = 0; c < NCHUNK; ++c) s += Sp[c*CB*CB + row*CB + col];
        v[j] = s * temp * invq[w] * invk[col];
    }
    float m = fmaxf(v[0], fmaxf(v[1], v[2]));
#pragma unroll
    for (int off = 16; off > 0; off >>= 1) m = fmaxf(m, __shfl_xor_sync(0xffffffffu, m, off));
    float e[3], sum = 0.f;
#pragma unroll
    for (int j = 0; j < 3; ++j) { e[j] = __expf(v[j] - m); sum += e[j]; }
#pragma unroll
    for (int off = 16; off > 0; off >>= 1) sum += __shfl_xor_sync(0xffffffffu, sum, off);
    float inv = 1.f / sum;
#pragma unroll
    for (int j = 0; j < 3; ++j) Ao[row*CB + lane + 32*j] = e[j] * inv;
}

// ---------------- K5: out = attn @ v (attn transposed in smem for LDS.128) ----------------
__global__ void __launch_bounds__(384, 2) k_av() {
    __shared__ __align__(16) u64   As2t[CB*98];    // [k][r] duplicated pairs, pitch 98
    __shared__ __align__(16) float Vs[12][128];
    const int nt = blockIdx.x;
    const int bh = blockIdx.y;
    const int b = bh >> 3, head = bh & 7;
    const int tid = threadIdx.x;
    const int rg = tid >> 5;
    const int tg = tid & 31;
    const int vrow = tid >> 5;
    const int vc4  = (tid & 31) * 4;

    const float* A = g_attn + (size_t)bh*CB*CB;
    for (int i = tid; i < CB*CB; i += 384) {
        int r = i / CB, c = i - r*CB;
        float a = A[i];
        As2t[c*98 + r] = pack2(a, a);
    }

    const float* V = g_v + (size_t)bh*CB*NTOK + nt*128;
    u64 acc[8][2];
#pragma unroll
    for (int i = 0; i < 8; ++i) { acc[i][0] = 0ull; acc[i][1] = 0ull; }

    float4 stage = *(const float4*)&V[(size_t)vrow*NTOK + vc4];

    for (int kc = 0; kc < 8; ++kc) {
        __syncthreads();
        *(float4*)&Vs[vrow][vc4] = stage;
        __syncthreads();
        if (kc + 1 < 8)
            stage = *(const float4*)&V[(size_t)((kc+1)*12 + vrow)*NTOK + vc4];
#pragma unroll
        for (int k = 0; k < 12; ++k) {
            u64 bv0 = *(const u64*)&Vs[k][2*tg];
            u64 bv1 = *(const u64*)&Vs[k][2*tg + 64];
            const ulonglong2* ap = (const ulonglong2*)&As2t[(kc*12 + k)*98 + rg*8];
            ulonglong2 a01 = ap[0], a23 = ap[1], a45 = ap[2], a67 = ap[3];
            u64 av[8] = {a01.x, a01.y, a23.x, a23.y, a45.x, a45.y, a67.x, a67.y};
#pragma unroll
            for (int i = 0; i < 8; ++i) {
                ffma2(acc[i][0], av[i], bv0);
                ffma2(acc[i][1], av[i], bv1);
            }
        }
    }
    float* outb = g_out1 + (size_t)b*CIN*HW;
#pragma unroll
    for (int g = 0; g < 2; ++g) {
        int group = rg*2 + g;
        int ci = group >> 2, Nh = group & 3;
        int ch = head*CSUB + ci;
        int y  = nt*4 + Nh;
#pragma unroll
        for (int jp = 0; jp < 2; ++jp) {
            float2 p0 = unpack2(acc[g*4+0][jp]);
            float2 p1 = unpack2(acc[g*4+1][jp]);
            float2 p2 = unpack2(acc[g*4+2][jp]);
            float2 p3 = unpack2(acc[g*4+3][jp]);
            size_t base = ((size_t)ch*HH + y)*WW + (size_t)(2*tg + 64*jp)*4;
            *(float4*)&outb[base]     = make_float4(p0.x, p1.x, p2.x, p3.x);
            *(float4*)&outb[base + 4] = make_float4(p0.y, p1.y, p2.y, p3.y);
        }
    }
}

// ---------------- K6: 1x1 proj conv ----------------
__global__ void __launch_bounds__(256, 3) k_proj(const float* __restrict__ wp, float* __restrict__ out) {
    __shared__ __align__(16) float Xs[48][256];
    __shared__ __align__(16) u64   W2[48][48];
    const int b   = blockIdx.z;
    const int px0 = blockIdx.x * 256;
    const int tid = threadIdx.x;
    const int lane = tid & 31;
    const int wgrp = tid >> 5;

    const float* xb = g_out1 + (size_t)b*CIN*HW + px0;
    for (int i = tid; i < 48*64; i += 256) {
        int row = i >> 6, c4 = (i & 63) * 4;
        cp16(&Xs[row][c4], xb + (size_t)row*HW + c4);
    }
    for (int i = tid; i < 48*48; i += 256) {
        int oc = i / 48, ic = i % 48;
        float w = wp[oc*48 + ic];
        W2[oc][ic] = pack2(w, w);
    }
    cp_wait_all();
    __syncthreads();

    u64 acc[6][4];
#pragma unroll
    for (int i = 0; i < 6; ++i)
#pragma unroll
        for (int j = 0; j < 4; ++j) acc[i][j] = 0ull;

#pragma unroll 4
    for (int k2 = 0; k2 < 24; ++k2) {
        const int k = 2*k2;
        u64 bv0[4], bv1[4];
#pragma unroll
        for (int j = 0; j < 4; ++j) {
            bv0[j] = *(const u64*)&Xs[k  ][2*lane + 64*j];
            bv1[j] = *(const u64*)&Xs[k+1][2*lane + 64*j];
        }
#pragma unroll
        for (int i = 0; i < 6; ++i) {
            const u64* wp2 = (const u64*)&W2[wgrp*6 + i][k];
            u64 a0 = wp2[0], a1 = wp2[1];
#pragma unroll
            for (int j = 0; j < 4; ++j) { ffma2(acc[i][j], a0, bv0[j]); ffma2(acc[i][j], a1, bv1[j]); }
        }
    }
    float* ob = out + (size_t)b*CIN*HW;
#pragma unroll
    for (int i = 0; i < 6; ++i) {
        int oc = wgrp*6 + i;
#pragma unroll
        for (int j = 0; j < 4; ++j)
            *(float2*)&ob[(size_t)oc*HW + px0 + 2*lane + 64*j] = unpack2(acc[i][j]);
    }
}

// ---------------- launch ----------------
extern "C" void kernel_launch(void* const* d_in, const int* in_sizes, int n_in,
                              void* d_out, int out_size) {
    (void)in_sizes; (void)n_in; (void)out_size;
    const float* x      = (const float*)d_in[0];
    const float* qkv_w  = (const float*)d_in[1];
    const float* dw_w   = (const float*)d_in[2];
    const float* proj_w = (const float*)d_in[3];
    const float* temper = (const float*)d_in[4];
    float* out = (float*)d_out;

    k_qkv <<<dim3(3, HW/256, B_), 256>>>(x, qkv_w);
    k_dw  <<<dim3(8, 16, B_*CQ), 256>>>(dw_w);
    k_gram<<<dim3(NCHUNK, BHTOT), 256>>>();
    k_soft<<<dim3(12, BHTOT), 256>>>(temper);
    k_av  <<<dim3(NTOK/128, BHTOT), 384>>>();
    k_proj<<<dim3(HW/256, 1, B_), 256>>>(proj_w, out);
}